// round 15
// baseline (speedup 1.0000x reference)
#include <cuda_runtime.h>
#include <cstdint>

// PScan: Y_t = A_t @ Y_{t-1} + X_t  (Y_0 = X_0), per (b,c) chain.
// Shapes: A,X,Y = [B=4, L=2048, C=16, 16, 16] fp32, row-major.
// FUSED single-pass chunked scan with decoupled lookback:
//   per 32-step chunk (1 warp): local (P,Z) -> lookback combine -> publish
//   inclusive carry -> replay chunk from exclusive carry, write Y.
// Split-k half-warps, f32x2 FFMA, cp.async A staging, X in registers.

#define BB 4
#define LL 2048
#define CC 16
#define TT 32
#define NCHUNK (LL / TT)            // 64
#define CHAINS (BB * CC)            // 64
#define TOTCHUNK (CHAINS * NCHUNK)  // 4096
#define STEP_STRIDE (CC * 256)

typedef unsigned long long u64;

__device__ float g_incl[TOTCHUNK * 256];     // inclusive carries
__device__ unsigned g_flag[TOTCHUNK];        // publish flags

__device__ __forceinline__ u64 ffma2(u64 a, u64 b, u64 c) {
    u64 d;
    asm("fma.rn.f32x2 %0, %1, %2, %3;" : "=l"(d) : "l"(a), "l"(b), "l"(c));
    return d;
}
__device__ __forceinline__ u64 add2(u64 a, u64 b) {
    u64 d;
    asm("add.rn.f32x2 %0, %1, %2;" : "=l"(d) : "l"(a), "l"(b));
    return d;
}
__device__ __forceinline__ u64 pack2(float lo, float hi) {
    u64 d;
    asm("mov.b64 %0, {%1, %2};" : "=l"(d) : "f"(lo), "f"(hi));
    return d;
}
__device__ __forceinline__ void unpack2(u64 v, float& lo, float& hi) {
    asm("mov.b64 {%0, %1}, %2;" : "=f"(lo), "=f"(hi) : "l"(v));
}

__device__ __forceinline__ void cp16(float* smem_dst, const float* gsrc) {
    uint32_t s = (uint32_t)__cvta_generic_to_shared(smem_dst);
    asm volatile("cp.async.ca.shared.global [%0], [%1], 16;\n" :: "r"(s), "l"(gsrc));
}
#define CP_COMMIT() asm volatile("cp.async.commit_group;\n" ::: "memory")
#define CP_WAIT0()  asm volatile("cp.async.wait_group 0;\n" ::: "memory")
#define CP_WAIT1()  asm volatile("cp.async.wait_group 1;\n" ::: "memory")

__device__ __forceinline__ float dot8(ulonglong2 a0, ulonglong2 a1, const u64* st)
{
    u64 acc0 = ffma2(a0.x, st[0], 0ull);
    u64 acc1 = ffma2(a0.y, st[1], 0ull);
    acc0 = ffma2(a1.x, st[2], acc0);
    acc1 = ffma2(a1.y, st[3], acc1);
    float lo, hi;
    unpack2(add2(acc0, acc1), lo, hi);
    return lo + hi;
}

// split-k step advancing Z and P states; xc = this lane's 8 X values
__device__ __forceinline__ void step_zp(const float* As, const float* xc,
                                        int h, int j, u64* zst, u64* pst)
{
    const float* Ah = As + h * 8;
    float zpL[8], zpH[8], ppL[8], ppH[8];
#pragma unroll
    for (int r = 0; r < 8; r++) {
        ulonglong2 a0 = *(const ulonglong2*)(Ah + r * 16);
        ulonglong2 a1 = *(const ulonglong2*)(Ah + r * 16 + 4);
        zpL[r] = dot8(a0, a1, zst);
        ppL[r] = dot8(a0, a1, pst);
        ulonglong2 b0 = *(const ulonglong2*)(Ah + (8 + r) * 16);
        ulonglong2 b1 = *(const ulonglong2*)(Ah + (8 + r) * 16 + 4);
        zpH[r] = dot8(b0, b1, zst);
        ppH[r] = dot8(b0, b1, pst);
    }
    float zn[8], pn[8];
#pragma unroll
    for (int r = 0; r < 8; r++) {
        float zs = h ? zpL[r] : zpH[r];
        float zr = __shfl_xor_sync(0xffffffffu, zs, 16);
        zn[r] = (h ? zpH[r] : zpL[r]) + zr + xc[r];
        float ps = h ? ppL[r] : ppH[r];
        float pr = __shfl_xor_sync(0xffffffffu, ps, 16);
        pn[r] = (h ? ppH[r] : ppL[r]) + pr;
    }
#pragma unroll
    for (int mm = 0; mm < 4; mm++) {
        zst[mm] = pack2(zn[2 * mm], zn[2 * mm + 1]);
        pst[mm] = pack2(pn[2 * mm], pn[2 * mm + 1]);
    }
}

// split-k step advancing Z only; writes new column values into zn[8]
__device__ __forceinline__ void step_z(const float* As, const float* xc,
                                       int h, int j, u64* zst, float* zn)
{
    const float* Ah = As + h * 8;
    float zpL[8], zpH[8];
#pragma unroll
    for (int r = 0; r < 8; r++) {
        ulonglong2 a0 = *(const ulonglong2*)(Ah + r * 16);
        ulonglong2 a1 = *(const ulonglong2*)(Ah + r * 16 + 4);
        zpL[r] = dot8(a0, a1, zst);
        ulonglong2 b0 = *(const ulonglong2*)(Ah + (8 + r) * 16);
        ulonglong2 b1 = *(const ulonglong2*)(Ah + (8 + r) * 16 + 4);
        zpH[r] = dot8(b0, b1, zst);
    }
#pragma unroll
    for (int r = 0; r < 8; r++) {
        float zs = h ? zpL[r] : zpH[r];
        float zr = __shfl_xor_sync(0xffffffffu, zs, 16);
        zn[r] = (h ? zpH[r] : zpL[r]) + zr + xc[r];
    }
#pragma unroll
    for (int mm = 0; mm < 4; mm++)
        zst[mm] = pack2(zn[2 * mm], zn[2 * mm + 1]);
}

// ============================================================================
__global__ void init_flags_kernel()
{
    const int i = blockIdx.x * blockDim.x + threadIdx.x;
    if (i < TOTCHUNK) g_flag[i] = 0u;
}

// ============================================================================
// Fused kernel: one warp per 32-step chunk.
// ============================================================================
__global__ void __launch_bounds__(64) pscan_fused_kernel(
    const float* __restrict__ A, const float* __restrict__ X,
    float* __restrict__ Y)
{
    __shared__ __align__(16) float smA[2][2][256];  // [warp][buf] A staging
    __shared__ __align__(16) float smP[2][256];     // [warp] local P tile

    const int wid  = threadIdx.x >> 5;
    const int lane = threadIdx.x & 31;
    const int w    = blockIdx.x * 2 + wid;
    const int chunk = w % NCHUNK;
    const int chain = w / NCHUNK;
    const int b = chain >> 4;
    const int c = chain & 15;
    const int t0 = chunk * TT;
    const int j = lane & 15;
    const int h = lane >> 4;

    const int base0 = ((b * LL + t0) * CC + c) * 256;
    const float* srcA = A + base0 + lane * 8;
    const float* xsrc = X + base0 + (8 * h) * 16 + j;

    // ---------------- local pass: chunk (P, Z) ----------------
    cp16(&smA[wid][0][lane * 8],     srcA);
    cp16(&smA[wid][0][lane * 8 + 4], srcA + 4);
    CP_COMMIT();

    float xa[8], xb[8];
#pragma unroll
    for (int r = 0; r < 8; r++) xa[r] = xsrc[r * 16];

    u64 zst[4], pst[4];
#pragma unroll
    for (int mm = 0; mm < 4; mm++) {
        zst[mm] = 0ull;
        int k0 = 8 * h + 2 * mm;
        pst[mm] = pack2(j == k0 ? 1.f : 0.f, j == k0 + 1 ? 1.f : 0.f);
    }

#pragma unroll 1
    for (int t = 0; t < TT; t += 2) {
        {
            const float* s2 = srcA + (t + 1) * STEP_STRIDE;
            float* dn = &smA[wid][(t + 1) & 1][lane * 8];
            cp16(dn, s2);
            cp16(dn + 4, s2 + 4);
            CP_COMMIT();
            const float* xs = xsrc + (t + 1) * STEP_STRIDE;
#pragma unroll
            for (int r = 0; r < 8; r++) xb[r] = xs[r * 16];
            CP_WAIT1();
            __syncwarp();
            step_zp(smA[wid][t & 1], xa, h, j, zst, pst);
            __syncwarp();
        }
        {
            if (t + 2 < TT) {
                const float* s2 = srcA + (t + 2) * STEP_STRIDE;
                float* dn = &smA[wid][t & 1][lane * 8];
                cp16(dn, s2);
                cp16(dn + 4, s2 + 4);
                CP_COMMIT();
                const float* xs = xsrc + (t + 2) * STEP_STRIDE;
#pragma unroll
                for (int r = 0; r < 8; r++) xa[r] = xs[r * 16];
                CP_WAIT1();
            } else {
                CP_COMMIT();
                CP_WAIT0();
            }
            __syncwarp();
            step_zp(smA[wid][(t + 1) & 1], xb, h, j, zst, pst);
            __syncwarp();
        }
    }

    // stage local P into smem (row-major) for the lookback combine
#pragma unroll
    for (int mm = 0; mm < 4; mm++) {
        const int row = 8 * h + 2 * mm;
        float lo, hi;
        unpack2(pst[mm], lo, hi);
        smP[wid][row * 16 + j] = lo;
        smP[wid][(row + 1) * 16 + j] = hi;
    }
    // local Z column values
    float zc[8];
#pragma unroll
    for (int mm = 0; mm < 4; mm++)
        unpack2(zst[mm], zc[2 * mm], zc[2 * mm + 1]);
    __syncwarp();

    // ---------------- lookback: incl = P @ prev + Z ----------------
    u64 prevSt[4];
    float incl[8];
    if (chunk == 0) {
#pragma unroll
        for (int mm = 0; mm < 4; mm++) prevSt[mm] = 0ull;
#pragma unroll
        for (int r = 0; r < 8; r++) incl[r] = zc[r];
    } else {
        const unsigned* fp = g_flag + (w - 1);
        unsigned f;
        do {
            asm volatile("ld.acquire.gpu.global.b32 %0, [%1];"
                         : "=r"(f) : "l"(fp) : "memory");
            if (!f) __nanosleep(40);
        } while (!f);
        const float* pv = g_incl + (size_t)(w - 1) * 256 + (8 * h) * 16 + j;
        float pr[8];
#pragma unroll
        for (int r = 0; r < 8; r++) pr[r] = __ldcg(pv + r * 16);
#pragma unroll
        for (int mm = 0; mm < 4; mm++)
            prevSt[mm] = pack2(pr[2 * mm], pr[2 * mm + 1]);
        u64 st2[4];
#pragma unroll
        for (int mm = 0; mm < 4; mm++) st2[mm] = prevSt[mm];
        step_z(smP[wid], zc, h, j, st2, incl);
    }

    // publish inclusive carry + flag (release)
    {
        float* ip = g_incl + (size_t)w * 256 + (8 * h) * 16 + j;
#pragma unroll
        for (int r = 0; r < 8; r++) ip[r * 16] = incl[r];
        __threadfence();
        __syncwarp();
        if (lane == 0) {
            unsigned one = 1u;
            asm volatile("st.release.gpu.global.b32 [%0], %1;"
                         :: "l"(g_flag + w), "r"(one) : "memory");
        }
    }

    // ---------------- replay: Y from exclusive carry ----------------
    cp16(&smA[wid][0][lane * 8],     srcA);
    cp16(&smA[wid][0][lane * 8 + 4], srcA + 4);
    CP_COMMIT();
#pragma unroll
    for (int r = 0; r < 8; r++) xa[r] = __ldcs(xsrc + r * 16);

    u64 yst[4];
#pragma unroll
    for (int mm = 0; mm < 4; mm++) yst[mm] = prevSt[mm];

    float* outc = Y + base0 + (8 * h) * 16 + j;
    float zn[8];

#pragma unroll 1
    for (int t = 0; t < TT; t += 2) {
        {
            const float* s2 = srcA + (t + 1) * STEP_STRIDE;
            float* dn = &smA[wid][(t + 1) & 1][lane * 8];
            cp16(dn, s2);
            cp16(dn + 4, s2 + 4);
            CP_COMMIT();
            const float* xs = xsrc + (t + 1) * STEP_STRIDE;
#pragma unroll
            for (int r = 0; r < 8; r++) xb[r] = __ldcs(xs + r * 16);
            CP_WAIT1();
            __syncwarp();
            step_z(smA[wid][t & 1], xa, h, j, yst, zn);
            float* out = outc + t * STEP_STRIDE;
#pragma unroll
            for (int r = 0; r < 8; r++) __stcs(out + r * 16, zn[r]);
            __syncwarp();
        }
        {
            if (t + 2 < TT) {
                const float* s2 = srcA + (t + 2) * STEP_STRIDE;
                float* dn = &smA[wid][t & 1][lane * 8];
                cp16(dn, s2);
                cp16(dn + 4, s2 + 4);
                CP_COMMIT();
                const float* xs = xsrc + (t + 2) * STEP_STRIDE;
#pragma unroll
                for (int r = 0; r < 8; r++) xa[r] = __ldcs(xs + r * 16);
                CP_WAIT1();
            } else {
                CP_COMMIT();
                CP_WAIT0();
            }
            __syncwarp();
            step_z(smA[wid][(t + 1) & 1], xb, h, j, yst, zn);
            float* out = outc + (t + 1) * STEP_STRIDE;
#pragma unroll
            for (int r = 0; r < 8; r++) __stcs(out + r * 16, zn[r]);
            __syncwarp();
        }
    }
}

// ============================================================================
extern "C" void kernel_launch(void* const* d_in, const int* in_sizes, int n_in,
                              void* d_out, int out_size)
{
    const float* A = (const float*)d_in[0];
    const float* X = (const float*)d_in[1];
    float* Y = (float*)d_out;

    init_flags_kernel<<<(TOTCHUNK + 511) / 512, 512>>>();
    pscan_fused_kernel<<<TOTCHUNK / 2, 64>>>(A, X, Y);
}

// round 16
// speedup vs baseline: 1.7180x; 1.7180x over previous
#include <cuda_runtime.h>
#include <cstdint>

// PScan: Y_t = A_t @ Y_{t-1} + X_t  (Y_0 = X_0), per (b,c) chain.
// Shapes: A,X,Y = [B=4, L=2048, C=16, 16, 16] fp32, row-major.
// TT=32 chunked scan. Phase1: split-k half-warps (R14). Phase2: two-level
// scan (R14). Phase3: NEW column-pair lanes, 2 matrices/warp, LDG.64/STG.64.

#define BB 4
#define LL 2048
#define CC 16
#define TT 32
#define NCHUNK (LL / TT)            // 64
#define CHAINS (BB * CC)            // 64
#define TOTCHUNK (CHAINS * NCHUNK)  // 4096
#define STEP_STRIDE (CC * 256)
#define SEG 16

typedef unsigned long long u64;

__device__ float g_Pagg[TOTCHUNK * 256];
__device__ float g_Zagg[TOTCHUNK * 256];
__device__ float g_carry[TOTCHUNK * 256];

__device__ __forceinline__ u64 ffma2(u64 a, u64 b, u64 c) {
    u64 d;
    asm("fma.rn.f32x2 %0, %1, %2, %3;" : "=l"(d) : "l"(a), "l"(b), "l"(c));
    return d;
}
__device__ __forceinline__ u64 add2(u64 a, u64 b) {
    u64 d;
    asm("add.rn.f32x2 %0, %1, %2;" : "=l"(d) : "l"(a), "l"(b));
    return d;
}
__device__ __forceinline__ u64 pack2(float lo, float hi) {
    u64 d;
    asm("mov.b64 %0, {%1, %2};" : "=l"(d) : "f"(lo), "f"(hi));
    return d;
}
__device__ __forceinline__ void unpack2(u64 v, float& lo, float& hi) {
    asm("mov.b64 {%0, %1}, %2;" : "=f"(lo), "=f"(hi) : "l"(v));
}

__device__ __forceinline__ void cp16(float* smem_dst, const float* gsrc) {
    uint32_t s = (uint32_t)__cvta_generic_to_shared(smem_dst);
    asm volatile("cp.async.ca.shared.global [%0], [%1], 16;\n" :: "r"(s), "l"(gsrc));
}
#define CP_COMMIT() asm volatile("cp.async.commit_group;\n" ::: "memory")
#define CP_WAIT0()  asm volatile("cp.async.wait_group 0;\n" ::: "memory")
#define CP_WAIT1()  asm volatile("cp.async.wait_group 1;\n" ::: "memory")
#define CP_WAIT3()  asm volatile("cp.async.wait_group 3;\n" ::: "memory")

// partial dot of one A-row k-half (a0,a1 = 4 f32x2) with packed state st[4]
__device__ __forceinline__ float dot8(ulonglong2 a0, ulonglong2 a1, const u64* st)
{
    u64 acc0 = ffma2(a0.x, st[0], 0ull);
    u64 acc1 = ffma2(a0.y, st[1], 0ull);
    acc0 = ffma2(a1.x, st[2], acc0);
    acc1 = ffma2(a1.y, st[3], acc1);
    float lo, hi;
    unpack2(add2(acc0, acc1), lo, hi);
    return lo + hi;
}

// split-k step advancing Z and P states; xc = this lane's 8 X values
__device__ __forceinline__ void step_zp(const float* As, const float* xc,
                                        int h, int j, u64* zst, u64* pst)
{
    const float* Ah = As + h * 8;
    float zpL[8], zpH[8], ppL[8], ppH[8];
#pragma unroll
    for (int r = 0; r < 8; r++) {
        ulonglong2 a0 = *(const ulonglong2*)(Ah + r * 16);
        ulonglong2 a1 = *(const ulonglong2*)(Ah + r * 16 + 4);
        zpL[r] = dot8(a0, a1, zst);
        ppL[r] = dot8(a0, a1, pst);
        ulonglong2 b0 = *(const ulonglong2*)(Ah + (8 + r) * 16);
        ulonglong2 b1 = *(const ulonglong2*)(Ah + (8 + r) * 16 + 4);
        zpH[r] = dot8(b0, b1, zst);
        ppH[r] = dot8(b0, b1, pst);
    }
    float zn[8], pn[8];
#pragma unroll
    for (int r = 0; r < 8; r++) {
        float zs = h ? zpL[r] : zpH[r];
        float zr = __shfl_xor_sync(0xffffffffu, zs, 16);
        zn[r] = (h ? zpH[r] : zpL[r]) + zr + xc[r];
        float ps = h ? ppL[r] : ppH[r];
        float pr = __shfl_xor_sync(0xffffffffu, ps, 16);
        pn[r] = (h ? ppH[r] : ppL[r]) + pr;
    }
#pragma unroll
    for (int mm = 0; mm < 4; mm++) {
        zst[mm] = pack2(zn[2 * mm], zn[2 * mm + 1]);
        pst[mm] = pack2(pn[2 * mm], pn[2 * mm + 1]);
    }
}

// split-k step advancing Z only; writes new column values into zn[8]
__device__ __forceinline__ void step_z(const float* As, const float* xc,
                                       int h, int j, u64* zst, float* zn)
{
    const float* Ah = As + h * 8;
    float zpL[8], zpH[8];
#pragma unroll
    for (int r = 0; r < 8; r++) {
        ulonglong2 a0 = *(const ulonglong2*)(Ah + r * 16);
        ulonglong2 a1 = *(const ulonglong2*)(Ah + r * 16 + 4);
        zpL[r] = dot8(a0, a1, zst);
        ulonglong2 b0 = *(const ulonglong2*)(Ah + (8 + r) * 16);
        ulonglong2 b1 = *(const ulonglong2*)(Ah + (8 + r) * 16 + 4);
        zpH[r] = dot8(b0, b1, zst);
    }
#pragma unroll
    for (int r = 0; r < 8; r++) {
        float zs = h ? zpL[r] : zpH[r];
        float zr = __shfl_xor_sync(0xffffffffu, zs, 16);
        zn[r] = (h ? zpH[r] : zpL[r]) + zr + xc[r];
    }
#pragma unroll
    for (int mm = 0; mm < 4; mm++)
        zst[mm] = pack2(zn[2 * mm], zn[2 * mm + 1]);
}

// ============================================================================
// Phase 1 (R13/R14-proven)
// ============================================================================
__global__ void __launch_bounds__(64) phase1_kernel(
    const float* __restrict__ A, const float* __restrict__ X)
{
    __shared__ __align__(16) float smA[2][2][256];

    const int wid  = threadIdx.x >> 5;
    const int lane = threadIdx.x & 31;
    const int w    = blockIdx.x * 2 + wid;
    const int chain = w / NCHUNK;
    const int chunk = w % NCHUNK;
    const int b = chain >> 4;
    const int c = chain & 15;
    const int t0 = chunk * TT;
    const int j = lane & 15;
    const int h = lane >> 4;

    const int base0 = ((b * LL + t0) * CC + c) * 256;
    const float* srcA = A + base0 + lane * 8;
    const float* xsrc = X + base0 + (8 * h) * 16 + j;

    cp16(&smA[wid][0][lane * 8],     srcA);
    cp16(&smA[wid][0][lane * 8 + 4], srcA + 4);
    CP_COMMIT();

    float xa[8], xb[8];
#pragma unroll
    for (int r = 0; r < 8; r++) xa[r] = xsrc[r * 16];

    u64 zst[4], pst[4];
#pragma unroll
    for (int mm = 0; mm < 4; mm++) {
        zst[mm] = 0ull;
        int k0 = 8 * h + 2 * mm;
        pst[mm] = pack2(j == k0 ? 1.f : 0.f, j == k0 + 1 ? 1.f : 0.f);
    }

#pragma unroll 1
    for (int t = 0; t < TT; t += 2) {
        {
            const float* s2 = srcA + (t + 1) * STEP_STRIDE;
            float* dn = &smA[wid][(t + 1) & 1][lane * 8];
            cp16(dn, s2);
            cp16(dn + 4, s2 + 4);
            CP_COMMIT();
            const float* xs = xsrc + (t + 1) * STEP_STRIDE;
#pragma unroll
            for (int r = 0; r < 8; r++) xb[r] = xs[r * 16];
            CP_WAIT1();
            __syncwarp();
            step_zp(smA[wid][t & 1], xa, h, j, zst, pst);
            __syncwarp();
        }
        {
            if (t + 2 < TT) {
                const float* s2 = srcA + (t + 2) * STEP_STRIDE;
                float* dn = &smA[wid][t & 1][lane * 8];
                cp16(dn, s2);
                cp16(dn + 4, s2 + 4);
                CP_COMMIT();
                const float* xs = xsrc + (t + 2) * STEP_STRIDE;
#pragma unroll
                for (int r = 0; r < 8; r++) xa[r] = xs[r * 16];
                CP_WAIT1();
            } else {
                CP_COMMIT();
                CP_WAIT0();
            }
            __syncwarp();
            step_zp(smA[wid][(t + 1) & 1], xb, h, j, zst, pst);
            __syncwarp();
        }
    }

    const int ab = w * 256;
#pragma unroll
    for (int mm = 0; mm < 4; mm++) {
        const int row = 8 * h + 2 * mm;
        float lo, hi;
        unpack2(zst[mm], lo, hi);
        g_Zagg[ab + row * 16 + j] = lo;
        g_Zagg[ab + (row + 1) * 16 + j] = hi;
        unpack2(pst[mm], lo, hi);
        g_Pagg[ab + row * 16 + j] = lo;
        g_Pagg[ab + (row + 1) * 16 + j] = hi;
    }
}

// ============================================================================
// Phase 2 (R14-proven): two-level scan, 1 block (4 warps) per chain.
// ============================================================================
__global__ void __launch_bounds__(128) phase2_kernel()
{
    __shared__ __align__(16) float sRing[4][2][256];
    __shared__ __align__(16) float sPseg[4][256];
    __shared__ __align__(16) float sZseg[4][256];
    __shared__ __align__(16) float sCar[4][256];

    const int chain = blockIdx.x;
    const int wid  = threadIdx.x >> 5;
    const int lane = threadIdx.x & 31;
    const int j = lane & 15;
    const int h = lane >> 4;

    const float* Pb = g_Pagg + (size_t)(chain * NCHUNK + wid * SEG) * 256;
    const float* Zb = g_Zagg + (size_t)(chain * NCHUNK + wid * SEG) * 256;

    cp16(&sRing[wid][0][lane * 8],     Pb + lane * 8);
    cp16(&sRing[wid][0][lane * 8 + 4], Pb + lane * 8 + 4);
    CP_COMMIT();

    u64 zst[4], pst[4];
#pragma unroll
    for (int mm = 0; mm < 4; mm++) {
        zst[mm] = 0ull;
        int k0 = 8 * h + 2 * mm;
        pst[mm] = pack2(j == k0 ? 1.f : 0.f, j == k0 + 1 ? 1.f : 0.f);
    }

#pragma unroll 1
    for (int c = 0; c < SEG; c++) {
        if (c + 1 < SEG) {
            const float* s2 = Pb + (c + 1) * 256 + lane * 8;
            float* dn = &sRing[wid][(c + 1) & 1][lane * 8];
            cp16(dn, s2);
            cp16(dn + 4, s2 + 4);
            CP_COMMIT();
            CP_WAIT1();
        } else {
            CP_COMMIT();
            CP_WAIT0();
        }
        float zc[8];
        const float* zs = Zb + c * 256 + (8 * h) * 16 + j;
#pragma unroll
        for (int r = 0; r < 8; r++) zc[r] = zs[r * 16];
        __syncwarp();
        step_zp(sRing[wid][c & 1], zc, h, j, zst, pst);
        __syncwarp();
    }

#pragma unroll
    for (int mm = 0; mm < 4; mm++) {
        const int row = 8 * h + 2 * mm;
        float lo, hi;
        unpack2(zst[mm], lo, hi);
        sZseg[wid][row * 16 + j] = lo;
        sZseg[wid][(row + 1) * 16 + j] = hi;
        unpack2(pst[mm], lo, hi);
        sPseg[wid][row * 16 + j] = lo;
        sPseg[wid][(row + 1) * 16 + j] = hi;
    }
    __syncthreads();

    if (wid == 0) {
        u64 car[4];
#pragma unroll
        for (int mm = 0; mm < 4; mm++) car[mm] = 0ull;
#pragma unroll 1
        for (int s = 0; s < 4; s++) {
#pragma unroll
            for (int mm = 0; mm < 4; mm++) {
                const int row = 8 * h + 2 * mm;
                float lo, hi;
                unpack2(car[mm], lo, hi);
                sCar[s][row * 16 + j] = lo;
                sCar[s][(row + 1) * 16 + j] = hi;
            }
            if (s < 3) {
                float zc[8];
#pragma unroll
                for (int r = 0; r < 8; r++) zc[r] = sZseg[s][(8 * h + r) * 16 + j];
                float dummy[8];
                step_z(sPseg[s], zc, h, j, car, dummy);
            }
        }
    }
    __syncthreads();

    cp16(&sRing[wid][0][lane * 8],     Pb + lane * 8);
    cp16(&sRing[wid][0][lane * 8 + 4], Pb + lane * 8 + 4);
    CP_COMMIT();

    u64 car[4];
#pragma unroll
    for (int mm = 0; mm < 4; mm++) {
        const int row = 8 * h + 2 * mm;
        car[mm] = pack2(sCar[wid][row * 16 + j], sCar[wid][(row + 1) * 16 + j]);
    }

    float* carDst = g_carry + (size_t)(chain * NCHUNK + wid * SEG) * 256;

#pragma unroll 1
    for (int c = 0; c < SEG; c++) {
        if (c + 1 < SEG) {
            const float* s2 = Pb + (c + 1) * 256 + lane * 8;
            float* dn = &sRing[wid][(c + 1) & 1][lane * 8];
            cp16(dn, s2);
            cp16(dn + 4, s2 + 4);
            CP_COMMIT();
            CP_WAIT1();
        } else {
            CP_COMMIT();
            CP_WAIT0();
        }
        float* dst = carDst + c * 256 + (8 * h) * 16 + j;
#pragma unroll
        for (int mm = 0; mm < 4; mm++) {
            float lo, hi;
            unpack2(car[mm], lo, hi);
            dst[(2 * mm) * 16] = lo;
            dst[(2 * mm + 1) * 16] = hi;
        }
        float zc[8];
        const float* zs = Zb + c * 256 + (8 * h) * 16 + j;
#pragma unroll
        for (int r = 0; r < 8; r++) zc[r] = zs[r * 16];
        __syncwarp();
        float dummy[8];
        step_z(sRing[wid][c & 1], zc, h, j, car, dummy);
        __syncwarp();
    }
}

// ============================================================================
// Phase 3 (NEW): column-pair lanes, 2 matrices per warp.
// Lane = (q, h, j2): matrix q (chunk w0+q), k-half h, columns {2j2, 2j2+1}.
// A staged per-matrix in padded smem tiles (TSTR stride -> conflict-free).
// X via LDG.64 prefetch, Y via STG.64 streaming, combine via shfl.xor(8).
// Reverse chunk order for L2 tail reuse.
// ============================================================================
#define P3D 4
#define TSTR 260   // padded tile stride in floats (1040B): disjoint bank quads

__global__ void __launch_bounds__(64) phase3_kernel(
    const float* __restrict__ A, const float* __restrict__ X,
    float* __restrict__ Y)
{
    __shared__ __align__(16) float smA[2][P3D][2 * TSTR];

    const int wid  = threadIdx.x >> 5;
    const int lane = threadIdx.x & 31;
    const int wp   = (gridDim.x - 1 - (int)blockIdx.x) * 2 + wid;  // warp id
    const int w0   = wp * 2;                     // chunks w0, w0+1 (same chain)
    const int chain = w0 / NCHUNK;
    const int b = chain >> 4;
    const int c = chain & 15;
    const int j2 = lane & 7;
    const int h  = (lane >> 3) & 1;
    const int q  = lane >> 4;

    const int w = w0 + q;
    const int t0 = (w % NCHUNK) * TT;
    const int baseq = ((b * LL + t0) * CC + c) * 256;

    // staging: lane stages row (lane&15) of tile q
    const float* srcA = A + baseq + (lane & 15) * 16;
    float* const tileBase = (float*)smA[wid] + q * TSTR;  // compute-read base
    const int stOff = q * TSTR + (lane & 15) * 16;        // staging offset

    // prologue: stage A steps 0..P3D-2
#pragma unroll
    for (int d = 0; d < P3D - 1; d++) {
        const float* s2 = srcA + d * STEP_STRIDE;
        float* dn = (float*)smA[wid][d] + stOff;
#pragma unroll
        for (int r4 = 0; r4 < 4; r4++) cp16(dn + r4 * 4, s2 + r4 * 4);
        CP_COMMIT();
    }

    // X source: rows 8h+r, cols (2j2, 2j2+1) as u64
    const float* xsrcf = X + baseq + (8 * h) * 16 + 2 * j2;

    u64 xa[8], xb[8];
#pragma unroll
    for (int r = 0; r < 8; r++)
        xa[r] = __ldcs((const u64*)(xsrcf + r * 16));

    // init state from carry: k-pairs per column, k in [8h, 8h+8)
    u64 za[4], zb[4];
    {
        const float* cb = g_carry + (size_t)w * 256 + (8 * h) * 16 + 2 * j2;
        float sA[8], sB[8];
#pragma unroll
        for (int r = 0; r < 8; r++) {
            u64 v = *(const u64*)(cb + r * 16);
            unpack2(v, sA[r], sB[r]);
        }
#pragma unroll
        for (int mm = 0; mm < 4; mm++) {
            za[mm] = pack2(sA[2 * mm], sA[2 * mm + 1]);
            zb[mm] = pack2(sB[2 * mm], sB[2 * mm + 1]);
        }
    }

    float* outf = Y + baseq + (8 * h) * 16 + 2 * j2;

#pragma unroll 1
    for (int t = 0; t < TT; t++) {
        // stage A[t + P3D - 1]; prefetch X[t+1]
        if (t + P3D - 1 < TT) {
            const float* s2 = srcA + (t + P3D - 1) * STEP_STRIDE;
            float* dn = (float*)smA[wid][(t + P3D - 1) % P3D] + stOff;
#pragma unroll
            for (int r4 = 0; r4 < 4; r4++) cp16(dn + r4 * 4, s2 + r4 * 4);
        }
        CP_COMMIT();
        u64* xcur = (t & 1) ? xb : xa;
        u64* xnxt = (t & 1) ? xa : xb;
        if (t + 1 < TT) {
            const float* xs = xsrcf + (t + 1) * STEP_STRIDE;
#pragma unroll
            for (int r = 0; r < 8; r++)
                xnxt[r] = __ldcs((const u64*)(xs + r * 16));
        }
        CP_WAIT3();
        __syncwarp();

        const float* Atile = (const float*)smA[wid][t % P3D] + q * TSTR;
        const float* Ah = Atile + h * 8;

        // dots: both columns share the A registers
        float aL[8], aH[8], bL[8], bH[8];
#pragma unroll
        for (int r = 0; r < 8; r++) {
            ulonglong2 a0 = *(const ulonglong2*)(Ah + r * 16);
            ulonglong2 a1 = *(const ulonglong2*)(Ah + r * 16 + 4);
            aL[r] = dot8(a0, a1, za);
            bL[r] = dot8(a0, a1, zb);
            ulonglong2 c0 = *(const ulonglong2*)(Ah + (8 + r) * 16);
            ulonglong2 c1 = *(const ulonglong2*)(Ah + (8 + r) * 16 + 4);
            aH[r] = dot8(c0, c1, za);
            bH[r] = dot8(c0, c1, zb);
        }

        // combine halves (xor 8: pairs within each 16-lane matrix group)
        float znA[8], znB[8];
#pragma unroll
        for (int r = 0; r < 8; r++) {
            float sA = h ? aL[r] : aH[r];
            float rA = __shfl_xor_sync(0xffffffffu, sA, 8);
            float sB = h ? bL[r] : bH[r];
            float rB = __shfl_xor_sync(0xffffffffu, sB, 8);
            float xlo, xhi;
            unpack2(xcur[r], xlo, xhi);
            znA[r] = (h ? aH[r] : aL[r]) + rA + xlo;
            znB[r] = (h ? bH[r] : bL[r]) + rB + xhi;
        }
#pragma unroll
        for (int mm = 0; mm < 4; mm++) {
            za[mm] = pack2(znA[2 * mm], znA[2 * mm + 1]);
            zb[mm] = pack2(znB[2 * mm], znB[2 * mm + 1]);
        }

        // streaming STG.64 of this lane's 8 (colA,colB) pairs
        float* out = outf + t * STEP_STRIDE;
#pragma unroll
        for (int r = 0; r < 8; r++)
            __stcs((u64*)(out + r * 16), pack2(znA[r], znB[r]));
    }
}

// ============================================================================
extern "C" void kernel_launch(void* const* d_in, const int* in_sizes, int n_in,
                              void* d_out, int out_size)
{
    const float* A = (const float*)d_in[0];
    const float* X = (const float*)d_in[1];
    float* Y = (float*)d_out;

    phase1_kernel<<<TOTCHUNK / 2, 64>>>(A, X);
    phase2_kernel<<<CHAINS, 128>>>();
    phase3_kernel<<<TOTCHUNK / 4, 64>>>(A, X, Y);
}

// round 17
// speedup vs baseline: 1.8306x; 1.0656x over previous
#include <cuda_runtime.h>
#include <cstdint>

// PScan: Y_t = A_t @ Y_{t-1} + X_t  (Y_0 = X_0), per (b,c) chain.
// Shapes: A,X,Y = [B=4, L=2048, C=16, 16, 16] fp32, row-major.
// TT=32 chunked scan; A via cp.async.CG (L1-bypass) smem ring; X in registers
// (L2-only loads); split-k half-warps, f32x2 FFMA; two-level phase2;
// phase3 reverse order (L2 tail reuse) + streaming stores.

#define BB 4
#define LL 2048
#define CC 16
#define TT 32
#define NCHUNK (LL / TT)            // 64
#define CHAINS (BB * CC)            // 64
#define TOTCHUNK (CHAINS * NCHUNK)  // 4096
#define STEP_STRIDE (CC * 256)
#define SEG 16

typedef unsigned long long u64;

__device__ float g_Pagg[TOTCHUNK * 256];
__device__ float g_Zagg[TOTCHUNK * 256];
__device__ float g_carry[TOTCHUNK * 256];

__device__ __forceinline__ u64 ffma2(u64 a, u64 b, u64 c) {
    u64 d;
    asm("fma.rn.f32x2 %0, %1, %2, %3;" : "=l"(d) : "l"(a), "l"(b), "l"(c));
    return d;
}
__device__ __forceinline__ u64 add2(u64 a, u64 b) {
    u64 d;
    asm("add.rn.f32x2 %0, %1, %2;" : "=l"(d) : "l"(a), "l"(b));
    return d;
}
__device__ __forceinline__ u64 pack2(float lo, float hi) {
    u64 d;
    asm("mov.b64 %0, {%1, %2};" : "=l"(d) : "f"(lo), "f"(hi));
    return d;
}
__device__ __forceinline__ void unpack2(u64 v, float& lo, float& hi) {
    asm("mov.b64 {%0, %1}, %2;" : "=f"(lo), "=f"(hi) : "l"(v));
}

// L1-bypass async copy (cg is 16B-only — exactly our granularity)
__device__ __forceinline__ void cp16(float* smem_dst, const float* gsrc) {
    uint32_t s = (uint32_t)__cvta_generic_to_shared(smem_dst);
    asm volatile("cp.async.cg.shared.global [%0], [%1], 16;\n" :: "r"(s), "l"(gsrc));
}
#define CP_COMMIT() asm volatile("cp.async.commit_group;\n" ::: "memory")
#define CP_WAIT0()  asm volatile("cp.async.wait_group 0;\n" ::: "memory")
#define CP_WAIT1()  asm volatile("cp.async.wait_group 1;\n" ::: "memory")
#define CP_WAIT3()  asm volatile("cp.async.wait_group 3;\n" ::: "memory")

// partial dot of one A-row k-half (a0,a1 = 4 f32x2) with packed state st[4]
__device__ __forceinline__ float dot8(ulonglong2 a0, ulonglong2 a1, const u64* st)
{
    u64 acc0 = ffma2(a0.x, st[0], 0ull);
    u64 acc1 = ffma2(a0.y, st[1], 0ull);
    acc0 = ffma2(a1.x, st[2], acc0);
    acc1 = ffma2(a1.y, st[3], acc1);
    float lo, hi;
    unpack2(add2(acc0, acc1), lo, hi);
    return lo + hi;
}

// split-k step advancing Z and P states; xc = this lane's 8 X values
__device__ __forceinline__ void step_zp(const float* As, const float* xc,
                                        int h, int j, u64* zst, u64* pst)
{
    const float* Ah = As + h * 8;
    float zpL[8], zpH[8], ppL[8], ppH[8];
#pragma unroll
    for (int r = 0; r < 8; r++) {
        ulonglong2 a0 = *(const ulonglong2*)(Ah + r * 16);
        ulonglong2 a1 = *(const ulonglong2*)(Ah + r * 16 + 4);
        zpL[r] = dot8(a0, a1, zst);
        ppL[r] = dot8(a0, a1, pst);
        ulonglong2 b0 = *(const ulonglong2*)(Ah + (8 + r) * 16);
        ulonglong2 b1 = *(const ulonglong2*)(Ah + (8 + r) * 16 + 4);
        zpH[r] = dot8(b0, b1, zst);
        ppH[r] = dot8(b0, b1, pst);
    }
    float zn[8], pn[8];
#pragma unroll
    for (int r = 0; r < 8; r++) {
        float zs = h ? zpL[r] : zpH[r];
        float zr = __shfl_xor_sync(0xffffffffu, zs, 16);
        zn[r] = (h ? zpH[r] : zpL[r]) + zr + xc[r];
        float ps = h ? ppL[r] : ppH[r];
        float pr = __shfl_xor_sync(0xffffffffu, ps, 16);
        pn[r] = (h ? ppH[r] : ppL[r]) + pr;
    }
#pragma unroll
    for (int mm = 0; mm < 4; mm++) {
        zst[mm] = pack2(zn[2 * mm], zn[2 * mm + 1]);
        pst[mm] = pack2(pn[2 * mm], pn[2 * mm + 1]);
    }
}

// split-k step advancing Z only; writes new column values into zn[8]
__device__ __forceinline__ void step_z(const float* As, const float* xc,
                                       int h, int j, u64* zst, float* zn)
{
    const float* Ah = As + h * 8;
    float zpL[8], zpH[8];
#pragma unroll
    for (int r = 0; r < 8; r++) {
        ulonglong2 a0 = *(const ulonglong2*)(Ah + r * 16);
        ulonglong2 a1 = *(const ulonglong2*)(Ah + r * 16 + 4);
        zpL[r] = dot8(a0, a1, zst);
        ulonglong2 b0 = *(const ulonglong2*)(Ah + (8 + r) * 16);
        ulonglong2 b1 = *(const ulonglong2*)(Ah + (8 + r) * 16 + 4);
        zpH[r] = dot8(b0, b1, zst);
    }
#pragma unroll
    for (int r = 0; r < 8; r++) {
        float zs = h ? zpL[r] : zpH[r];
        float zr = __shfl_xor_sync(0xffffffffu, zs, 16);
        zn[r] = (h ? zpH[r] : zpL[r]) + zr + xc[r];
    }
#pragma unroll
    for (int mm = 0; mm < 4; mm++)
        zst[mm] = pack2(zn[2 * mm], zn[2 * mm + 1]);
}

// ============================================================================
// Phase 1 (R14 structure; cg staging, L2-only X loads)
// ============================================================================
__global__ void __launch_bounds__(64) phase1_kernel(
    const float* __restrict__ A, const float* __restrict__ X)
{
    __shared__ __align__(16) float smA[2][2][256];

    const int wid  = threadIdx.x >> 5;
    const int lane = threadIdx.x & 31;
    const int w    = blockIdx.x * 2 + wid;
    const int chain = w / NCHUNK;
    const int chunk = w % NCHUNK;
    const int b = chain >> 4;
    const int c = chain & 15;
    const int t0 = chunk * TT;
    const int j = lane & 15;
    const int h = lane >> 4;

    const int base0 = ((b * LL + t0) * CC + c) * 256;
    const float* srcA = A + base0 + lane * 8;
    const float* xsrc = X + base0 + (8 * h) * 16 + j;

    cp16(&smA[wid][0][lane * 8],     srcA);
    cp16(&smA[wid][0][lane * 8 + 4], srcA + 4);
    CP_COMMIT();

    float xa[8], xb[8];
#pragma unroll
    for (int r = 0; r < 8; r++) xa[r] = __ldcg(xsrc + r * 16);

    u64 zst[4], pst[4];
#pragma unroll
    for (int mm = 0; mm < 4; mm++) {
        zst[mm] = 0ull;
        int k0 = 8 * h + 2 * mm;
        pst[mm] = pack2(j == k0 ? 1.f : 0.f, j == k0 + 1 ? 1.f : 0.f);
    }

#pragma unroll 1
    for (int t = 0; t < TT; t += 2) {
        {
            const float* s2 = srcA + (t + 1) * STEP_STRIDE;
            float* dn = &smA[wid][(t + 1) & 1][lane * 8];
            cp16(dn, s2);
            cp16(dn + 4, s2 + 4);
            CP_COMMIT();
            const float* xs = xsrc + (t + 1) * STEP_STRIDE;
#pragma unroll
            for (int r = 0; r < 8; r++) xb[r] = __ldcg(xs + r * 16);
            CP_WAIT1();
            __syncwarp();
            step_zp(smA[wid][t & 1], xa, h, j, zst, pst);
            __syncwarp();
        }
        {
            if (t + 2 < TT) {
                const float* s2 = srcA + (t + 2) * STEP_STRIDE;
                float* dn = &smA[wid][t & 1][lane * 8];
                cp16(dn, s2);
                cp16(dn + 4, s2 + 4);
                CP_COMMIT();
                const float* xs = xsrc + (t + 2) * STEP_STRIDE;
#pragma unroll
                for (int r = 0; r < 8; r++) xa[r] = __ldcg(xs + r * 16);
                CP_WAIT1();
            } else {
                CP_COMMIT();
                CP_WAIT0();
            }
            __syncwarp();
            step_zp(smA[wid][(t + 1) & 1], xb, h, j, zst, pst);
            __syncwarp();
        }
    }

    const int ab = w * 256;
#pragma unroll
    for (int mm = 0; mm < 4; mm++) {
        const int row = 8 * h + 2 * mm;
        float lo, hi;
        unpack2(zst[mm], lo, hi);
        g_Zagg[ab + row * 16 + j] = lo;
        g_Zagg[ab + (row + 1) * 16 + j] = hi;
        unpack2(pst[mm], lo, hi);
        g_Pagg[ab + row * 16 + j] = lo;
        g_Pagg[ab + (row + 1) * 16 + j] = hi;
    }
}

// ============================================================================
// Phase 2 (R14-proven): two-level scan, 1 block (4 warps) per chain.
// ============================================================================
__global__ void __launch_bounds__(128) phase2_kernel()
{
    __shared__ __align__(16) float sRing[4][2][256];
    __shared__ __align__(16) float sPseg[4][256];
    __shared__ __align__(16) float sZseg[4][256];
    __shared__ __align__(16) float sCar[4][256];

    const int chain = blockIdx.x;
    const int wid  = threadIdx.x >> 5;
    const int lane = threadIdx.x & 31;
    const int j = lane & 15;
    const int h = lane >> 4;

    const float* Pb = g_Pagg + (size_t)(chain * NCHUNK + wid * SEG) * 256;
    const float* Zb = g_Zagg + (size_t)(chain * NCHUNK + wid * SEG) * 256;

    cp16(&sRing[wid][0][lane * 8],     Pb + lane * 8);
    cp16(&sRing[wid][0][lane * 8 + 4], Pb + lane * 8 + 4);
    CP_COMMIT();

    u64 zst[4], pst[4];
#pragma unroll
    for (int mm = 0; mm < 4; mm++) {
        zst[mm] = 0ull;
        int k0 = 8 * h + 2 * mm;
        pst[mm] = pack2(j == k0 ? 1.f : 0.f, j == k0 + 1 ? 1.f : 0.f);
    }

#pragma unroll 1
    for (int c = 0; c < SEG; c++) {
        if (c + 1 < SEG) {
            const float* s2 = Pb + (c + 1) * 256 + lane * 8;
            float* dn = &sRing[wid][(c + 1) & 1][lane * 8];
            cp16(dn, s2);
            cp16(dn + 4, s2 + 4);
            CP_COMMIT();
            CP_WAIT1();
        } else {
            CP_COMMIT();
            CP_WAIT0();
        }
        float zc[8];
        const float* zs = Zb + c * 256 + (8 * h) * 16 + j;
#pragma unroll
        for (int r = 0; r < 8; r++) zc[r] = zs[r * 16];
        __syncwarp();
        step_zp(sRing[wid][c & 1], zc, h, j, zst, pst);
        __syncwarp();
    }

#pragma unroll
    for (int mm = 0; mm < 4; mm++) {
        const int row = 8 * h + 2 * mm;
        float lo, hi;
        unpack2(zst[mm], lo, hi);
        sZseg[wid][row * 16 + j] = lo;
        sZseg[wid][(row + 1) * 16 + j] = hi;
        unpack2(pst[mm], lo, hi);
        sPseg[wid][row * 16 + j] = lo;
        sPseg[wid][(row + 1) * 16 + j] = hi;
    }
    __syncthreads();

    if (wid == 0) {
        u64 car[4];
#pragma unroll
        for (int mm = 0; mm < 4; mm++) car[mm] = 0ull;
#pragma unroll 1
        for (int s = 0; s < 4; s++) {
#pragma unroll
            for (int mm = 0; mm < 4; mm++) {
                const int row = 8 * h + 2 * mm;
                float lo, hi;
                unpack2(car[mm], lo, hi);
                sCar[s][row * 16 + j] = lo;
                sCar[s][(row + 1) * 16 + j] = hi;
            }
            if (s < 3) {
                float zc[8];
#pragma unroll
                for (int r = 0; r < 8; r++) zc[r] = sZseg[s][(8 * h + r) * 16 + j];
                float dummy[8];
                step_z(sPseg[s], zc, h, j, car, dummy);
            }
        }
    }
    __syncthreads();

    cp16(&sRing[wid][0][lane * 8],     Pb + lane * 8);
    cp16(&sRing[wid][0][lane * 8 + 4], Pb + lane * 8 + 4);
    CP_COMMIT();

    u64 car[4];
#pragma unroll
    for (int mm = 0; mm < 4; mm++) {
        const int row = 8 * h + 2 * mm;
        car[mm] = pack2(sCar[wid][row * 16 + j], sCar[wid][(row + 1) * 16 + j]);
    }

    float* carDst = g_carry + (size_t)(chain * NCHUNK + wid * SEG) * 256;

#pragma unroll 1
    for (int c = 0; c < SEG; c++) {
        if (c + 1 < SEG) {
            const float* s2 = Pb + (c + 1) * 256 + lane * 8;
            float* dn = &sRing[wid][(c + 1) & 1][lane * 8];
            cp16(dn, s2);
            cp16(dn + 4, s2 + 4);
            CP_COMMIT();
            CP_WAIT1();
        } else {
            CP_COMMIT();
            CP_WAIT0();
        }
        float* dst = carDst + c * 256 + (8 * h) * 16 + j;
#pragma unroll
        for (int mm = 0; mm < 4; mm++) {
            float lo, hi;
            unpack2(car[mm], lo, hi);
            dst[(2 * mm) * 16] = lo;
            dst[(2 * mm + 1) * 16] = hi;
        }
        float zc[8];
        const float* zs = Zb + c * 256 + (8 * h) * 16 + j;
#pragma unroll
        for (int r = 0; r < 8; r++) zc[r] = zs[r * 16];
        __syncwarp();
        float dummy[8];
        step_z(sRing[wid][c & 1], zc, h, j, car, dummy);
        __syncwarp();
    }
}

// ============================================================================
// Phase 3 (R14 structure; cg staging): reverse chunk order, depth-4 ring,
// X via __ldcs register prefetch, Y via streaming STG.32.
// ============================================================================
#define P3D 4

__global__ void __launch_bounds__(64) phase3_kernel(
    const float* __restrict__ A, const float* __restrict__ X,
    float* __restrict__ Y)
{
    __shared__ __align__(16) float smA[2][P3D][256];

    const int wid  = threadIdx.x >> 5;
    const int lane = threadIdx.x & 31;
    const int w    = (gridDim.x - 1 - blockIdx.x) * 2 + wid;
    const int chain = w / NCHUNK;
    const int chunk = w % NCHUNK;
    const int b = chain >> 4;
    const int c = chain & 15;
    const int t0 = chunk * TT;
    const int j = lane & 15;
    const int h = lane >> 4;

    const int base0 = ((b * LL + t0) * CC + c) * 256;
    const float* srcA = A + base0 + lane * 8;
    const float* xsrc = X + base0 + (8 * h) * 16 + j;

#pragma unroll
    for (int d = 0; d < P3D - 1; d++) {
        const float* s2 = srcA + d * STEP_STRIDE;
        cp16(&smA[wid][d][lane * 8],     s2);
        cp16(&smA[wid][d][lane * 8 + 4], s2 + 4);
        CP_COMMIT();
    }

    float xa[8], xb[8];
#pragma unroll
    for (int r = 0; r < 8; r++) xa[r] = __ldcs(xsrc + r * 16);

    u64 zst[4];
    {
        const int cb = w * 256;
#pragma unroll
        for (int mm = 0; mm < 4; mm++) {
            const int row = 8 * h + 2 * mm;
            zst[mm] = pack2(g_carry[cb + row * 16 + j],
                            g_carry[cb + (row + 1) * 16 + j]);
        }
    }

    float* outc = Y + base0 + (8 * h) * 16 + j;
    float zn[8];

#pragma unroll 1
    for (int t = 0; t < TT; t += 2) {
        {
            if (t + P3D - 1 < TT) {
                const float* s2 = srcA + (t + P3D - 1) * STEP_STRIDE;
                float* dn = &smA[wid][(t + P3D - 1) % P3D][lane * 8];
                cp16(dn, s2);
                cp16(dn + 4, s2 + 4);
            }
            CP_COMMIT();
            const float* xs = xsrc + (t + 1) * STEP_STRIDE;
#pragma unroll
            for (int r = 0; r < 8; r++) xb[r] = __ldcs(xs + r * 16);
            CP_WAIT3();
            __syncwarp();
            step_z(smA[wid][t % P3D], xa, h, j, zst, zn);
            float* out = outc + t * STEP_STRIDE;
#pragma unroll
            for (int r = 0; r < 8; r++) __stcs(out + r * 16, zn[r]);
        }
        {
            if (t + P3D < TT) {
                const float* s2 = srcA + (t + P3D) * STEP_STRIDE;
                float* dn = &smA[wid][(t + P3D) % P3D][lane * 8];
                cp16(dn, s2);
                cp16(dn + 4, s2 + 4);
            }
            CP_COMMIT();
            if (t + 2 < TT) {
                const float* xs = xsrc + (t + 2) * STEP_STRIDE;
#pragma unroll
                for (int r = 0; r < 8; r++) xa[r] = __ldcs(xs + r * 16);
            }
            CP_WAIT3();
            __syncwarp();
            step_z(smA[wid][(t + 1) % P3D], xb, h, j, zst, zn);
            float* out = outc + (t + 1) * STEP_STRIDE;
#pragma unroll
            for (int r = 0; r < 8; r++) __stcs(out + r * 16, zn[r]);
        }
    }
}

// ============================================================================
extern "C" void kernel_launch(void* const* d_in, const int* in_sizes, int n_in,
                              void* d_out, int out_size)
{
    const float* A = (const float*)d_in[0];
    const float* X = (const float*)d_in[1];
    float* Y = (float*)d_out;

    phase1_kernel<<<TOTCHUNK / 2, 64>>>(A, X);
    phase2_kernel<<<CHAINS, 128>>>();
    phase3_kernel<<<TOTCHUNK / 2, 64>>>(A, X, Y);
}